// round 15
// baseline (speedup 1.0000x reference)
#include <cuda_runtime.h>

typedef unsigned long long u64;
typedef unsigned int u32;

#define NEG_INF_F (-3.4028234663852886e38f)
#define CCAP  2048
#define GCAP  1024
#define HCAP  4096
#define TOPN  64
#define SPLITB 16
#define MAXB  256
#define NTA   256
#define NTB   256
#define NTC   512
#define PRNG_SCHEME 2   // validated PASS

__device__ float g_T[MAXB], g_M[MAXB];
__device__ float g_sexp[MAXB*SPLITB];
__device__ u64 g_cand[(size_t)MAXB*GCAP];
__device__ int g_cnt[MAXB];

__device__ __forceinline__ u32 fkey(float f){
  u32 u = __float_as_uint(f);
  return (u & 0x80000000u) ? ~u : (u | 0x80000000u);
}
__device__ __forceinline__ float fdec(u32 s){
  u32 u = (s & 0x80000000u) ? (s ^ 0x80000000u) : ~s;
  return __uint_as_float(u);
}
__device__ __forceinline__ void tfb(u32& x0, u32& x1, int r0, int r1, int r2, int r3){
  x0 += x1; x1 = __funnelshift_l(x1, x1, r0); x1 ^= x0;
  x0 += x1; x1 = __funnelshift_l(x1, x1, r1); x1 ^= x0;
  x0 += x1; x1 = __funnelshift_l(x1, x1, r2); x1 ^= x0;
  x0 += x1; x1 = __funnelshift_l(x1, x1, r3); x1 ^= x0;
}
__device__ __forceinline__ void threefry42(u32 c0, u32 c1, u32& o0, u32& o1){
  const u32 k0 = 0u, k1 = 42u, k2 = 0x1BD11BDAu ^ k0 ^ k1;
  u32 x0 = c0 + k0, x1 = c1 + k1;
  tfb(x0,x1,13,15,26,6);  x0 += k1; x1 += k2 + 1u;
  tfb(x0,x1,17,29,16,24); x0 += k2; x1 += k0 + 2u;
  tfb(x0,x1,13,15,26,6);  x0 += k0; x1 += k1 + 3u;
  tfb(x0,x1,17,29,16,24); x0 += k1; x1 += k2 + 4u;
  tfb(x0,x1,13,15,26,6);  x0 += k2; x1 += k0 + 5u;
  o0 = x0; o1 = x1;
}
__device__ __forceinline__ float gumbel_at(u64 j, u64 half){
  u32 o0, o1, bits;
#if PRNG_SCHEME == 1
  if (j < half){ threefry42((u32)j, (u32)(j + half), o0, o1); bits = o0; }
  else         { threefry42((u32)(j - half), (u32)j, o0, o1); bits = o1; }
#else
  threefry42((u32)(j >> 32), (u32)j, o0, o1); bits = o0 ^ o1;
#endif
  float u = __uint_as_float((bits >> 9) | 0x3f800000u) - 1.0f;
  float v = fmaxf(1e-10f, u + 1e-10f);
  return -logf(-logf(v));
}

// ---- KA: sampled stats (1/64 of row) -> threshold + exp-shift ----
__global__ void __launch_bounds__(NTA)
ka_sample(const float* __restrict__ logits, int V)
{
  const int row = blockIdx.x, tid = threadIdx.x, lane = tid & 31, wid = tid >> 5;
  if (tid == 0) g_cnt[row] = 0;
  const float4* l4 = (const float4*)(logits + (size_t)row * V);
  const int n4 = V >> 2;
  __shared__ float r0[8], r1[8], r2[8];
  __shared__ int r3[8];
  float m = __int_as_float(0xff800000), sum = 0.f, ssq = 0.f;
  int ns = 0;
  for (int i = tid; i < n4; i += NTA * 64){
    float4 v = l4[i];
    m = fmaxf(m, fmaxf(fmaxf(v.x, v.y), fmaxf(v.z, v.w)));
    sum += (v.x + v.y) + (v.z + v.w);
    ssq += v.x*v.x + v.y*v.y + v.z*v.z + v.w*v.w;
    ns += 4;
  }
  #pragma unroll
  for (int o = 16; o; o >>= 1){
    m   = fmaxf(m, __shfl_down_sync(~0u, m, o));
    sum += __shfl_down_sync(~0u, sum, o);
    ssq += __shfl_down_sync(~0u, ssq, o);
    ns  += __shfl_down_sync(~0u, ns, o);
  }
  if (lane == 0){ r0[wid] = m; r1[wid] = sum; r2[wid] = ssq; r3[wid] = ns; }
  __syncthreads();
  if (tid == 0){
    for (int w = 1; w < NTA/32; w++){
      m = fmaxf(m, r0[w]); sum += r1[w]; ssq += r2[w]; ns += r3[w];
    }
    float mu = sum / fmaxf((float)ns, 1.f);
    float sig = sqrtf(fmaxf(ssq / fmaxf((float)ns, 1.f) - mu * mu, 0.f));
    g_T[row] = mu + 3.0f * sig;
    g_M[row] = m;
  }
}

// ---- KB: one full pass — sumexp (shift m̂) + tight-threshold gather (×2 unroll, any-hit fast path) ----
__global__ void __launch_bounds__(NTB)
kb_gather(const float* __restrict__ logits, int V, int Vs)
{
  const int row = blockIdx.x / SPLITB, sl = blockIdx.x % SPLITB;
  const int tid = threadIdx.x, lane = tid & 31, wid = tid >> 5;
  const float* lrow = logits + (size_t)row * V;
  const float T = g_T[row], bm = g_M[row];
  int e0 = sl * Vs; if (e0 > V) e0 = V;
  int e1 = e0 + Vs; if (e1 > V) e1 = V;
  const int f0 = e0 >> 2, f1 = e1 >> 2;
  const float4* l4 = (const float4*)lrow;
  __shared__ float r0[NTB/32];
  float se = 0.f;
  const int stride = NTB * 2;
  const int iters = (f1 - f0 + stride - 1) / stride;
  for (int t = 0; t < iters; t++){
    int i = f0 + t * stride + tid;
    int j = i + NTB;
    bool in1 = (i < f1), in2 = (j < f1);
    float4 v1 = in1 ? l4[i] : make_float4(-1e30f, -1e30f, -1e30f, -1e30f);
    float4 v2 = in2 ? l4[j] : make_float4(-1e30f, -1e30f, -1e30f, -1e30f);
    if (in1) se += __expf(v1.x-bm) + __expf(v1.y-bm) + __expf(v1.z-bm) + __expf(v1.w-bm);
    if (in2) se += __expf(v2.x-bm) + __expf(v2.y-bm) + __expf(v2.z-bm) + __expf(v2.w-bm);
    float xs[8] = {v1.x, v1.y, v1.z, v1.w, v2.x, v2.y, v2.z, v2.w};
    bool pr[8];
    #pragma unroll
    for (int c2 = 0; c2 < 4; c2++){ pr[c2] = in1 && (xs[c2] >= T); pr[c2+4] = in2 && (xs[c2+4] >= T); }
    bool any = pr[0]|pr[1]|pr[2]|pr[3]|pr[4]|pr[5]|pr[6]|pr[7];
    u32 anyb = __ballot_sync(~0u, any);
    if (anyb){
      u32 mk[8]; int pc[8];
      #pragma unroll
      for (int c2 = 0; c2 < 8; c2++){ mk[c2] = __ballot_sync(~0u, pr[c2]); pc[c2] = __popc(mk[c2]); }
      int total = 0;
      #pragma unroll
      for (int c2 = 0; c2 < 8; c2++) total += pc[c2];
      int base = 0;
      if (lane == 0) base = atomicAdd(&g_cnt[row], total);
      base = __shfl_sync(~0u, base, 0);
      int run = 0;
      int bi1 = i << 2, bi2 = j << 2;
      u32 lt = (1u << lane) - 1u;
      #pragma unroll
      for (int c2 = 0; c2 < 8; c2++){
        if (mk[c2] & (1u << lane)){
          int p = base + run + __popc(mk[c2] & lt);
          int gidx = (c2 < 4) ? (bi1 + c2) : (bi2 + c2 - 4);
          if (p < GCAP) g_cand[(size_t)row*GCAP + p] = ((u64)fkey(xs[c2]) << 32) | (u32)~(u32)gidx;
        }
        run += pc[c2];
      }
    }
  }
  for (int i = (f1 << 2) + tid; i < e1; i += NTB){
    float x = lrow[i];
    se += __expf(x - bm);
    if (x >= T){
      int p = atomicAdd(&g_cnt[row], 1);
      if (p < GCAP) g_cand[(size_t)row*GCAP + p] = ((u64)fkey(x) << 32) | (u32)~(u32)i;
    }
  }
  #pragma unroll
  for (int o = 16; o; o >>= 1) se += __shfl_down_sync(~0u, se, o);
  if (lane == 0) r0[wid] = se;
  __syncthreads();
  if (tid == 0){
    for (int w = 1; w < NTB/32; w++) se += r0[w];
    g_sexp[row*SPLITB+sl] = se;
  }
}

// ---- KC: per-row finish (hash, validate, sorts, outputs) ----
__global__ void __launch_bounds__(NTC)
kc_final(const float* __restrict__ logits, const float* __restrict__ temperature,
         const float* __restrict__ presence, const float* __restrict__ frequency,
         const float* __restrict__ repetition, const float* __restrict__ top_p,
         const int* __restrict__ prompt_ids, const int* __restrict__ out_tok,
         const int* __restrict__ out_lens, const int* __restrict__ stop_ids,
         const int* __restrict__ min_toks, const int* __restrict__ top_k,
         float* __restrict__ out, int B, int V, int P, int O, int S, int MN)
{
  extern __shared__ unsigned char smraw[];
  u64* cbuf = (u64*)smraw;            // CCAP
  u32* hkey = (u32*)(cbuf + CCAP);    // HCAP
  u32* hval = hkey + HCAP;            // HCAP
  __shared__ int sh_cnt, sh_unp;
  __shared__ float e_val[TOPN], e_gum[TOPN], e_exp[TOPN];
  __shared__ u32 e_idx[TOPN];

  const int row = blockIdx.x;
  const int tid = threadIdx.x, lane = tid & 31;
  const float* lrow = logits + (size_t)row * V;

  float Z = 0.f;
  #pragma unroll
  for (int s = 0; s < SPLITB; s++) Z += g_sexp[row*SPLITB+s];
  const float logZ = logf(Z);
  const float mf = g_M[row];

  int c_raw = g_cnt[row];
  int c = (c_raw < GCAP) ? c_raw : GCAP;
  for (int i = tid; i < c; i += NTC) cbuf[i] = g_cand[(size_t)row*GCAP + i];

  for (int i = tid; i < HCAP; i += NTC){ hkey[i] = 0xFFFFFFFFu; hval[i] = 0u; }
  __syncthreads();
  const int olen = out_lens[row];
  const bool penal = olen < min_toks[row];
  auto insert = [&](int id, u32 orb, u32 add){
    u32 uid = (u32)id, h = ((uid * 2654435761u) >> 16) & (HCAP - 1);
    for (;;){
      u32 k = hkey[h];
      if (k == uid) break;
      if (k == 0xFFFFFFFFu){
        u32 old = atomicCAS(&hkey[h], 0xFFFFFFFFu, uid);
        if (old == 0xFFFFFFFFu || old == uid) break;
      }
      h = (h + 1) & (HCAP - 1);
    }
    if (orb) atomicOr(&hval[h], orb);
    if (add) atomicAdd(&hval[h], add);
  };
  for (int i = tid; i < P; i += NTC) insert(prompt_ids[(size_t)row*P + i], 1u<<16, 0u);
  for (int i = tid; i < O; i += NTC) if (i < olen) insert(out_tok[(size_t)row*O + i], 0u, 1u);
  if (penal) for (int i = tid; i < S; i += NTC) insert(stop_ids[(size_t)row*S + i], 1u<<17, 0u);
  __syncthreads();

  auto probe = [&](u32 idx)->u32{
    u32 h = ((idx * 2654435761u) >> 16) & (HCAP - 1);
    for (;;){
      u32 kk = hkey[h];
      if (kk == idx) return hval[h];
      if (kk == 0xFFFFFFFFu) return 0u;
      h = (h + 1) & (HCAP - 1);
    }
  };

  if (tid == 0){ sh_unp = 0; }
  __syncthreads();
  {
    int unp = 0;
    for (int i = tid; i < c; i += NTC){
      u32 idx = ~(u32)cbuf[i];
      if (probe(idx) == 0u) unp++;
    }
    #pragma unroll
    for (int o = 16; o; o >>= 1) unp += __shfl_down_sync(~0u, unp, o);
    if (lane == 0 && unp) atomicAdd(&sh_unp, unp);
  }
  __syncthreads();
  int needU = (64 < V) ? 64 : V;
  bool valid = (c_raw <= GCAP) && (c >= ((MN < V) ? MN : V)) && (sh_unp >= needU);

  if (!valid){
    int minc = P + O + S + TOPN; if (minc > V) minc = V;
    float lo = -1e30f, hi = mf + 1.f;
    float T = g_T[row];
    for (int it = 0; it < 60; it++){
      if (tid == 0) sh_cnt = 0;
      __syncthreads();
      int cc = 0;
      for (int i = tid; i < V; i += NTC) if (lrow[i] >= T) cc++;
      #pragma unroll
      for (int o = 16; o; o >>= 1) cc += __shfl_down_sync(~0u, cc, o);
      if (lane == 0 && cc) atomicAdd(&sh_cnt, cc);
      __syncthreads();
      int tot = sh_cnt;
      if (tot >= minc && tot <= CCAP) break;
      if (tot > CCAP) lo = T; else hi = T;
      T = 0.5f * (lo + hi);
      __syncthreads();
    }
    if (tid == 0) sh_cnt = 0;
    __syncthreads();
    int vpad = V + (NTC - V % NTC) % NTC;
    for (int i = tid; i < vpad; i += NTC){
      bool pred = (i < V) && (lrow[i] >= T);
      float x = pred ? lrow[i] : 0.f;
      u32 mk = __ballot_sync(~0u, pred);
      if (mk){
        int leader = __ffs(mk) - 1, pos = 0;
        if (lane == leader) pos = atomicAdd(&sh_cnt, __popc(mk));
        pos = __shfl_sync(~0u, pos, leader);
        if (pred){
          int p = pos + __popc(mk & ((1u << lane) - 1u));
          if (p < CCAP) cbuf[p] = ((u64)fkey(x) << 32) | (u32)~(u32)i;
        }
      }
    }
    __syncthreads();
    c = sh_cnt; if (c > CCAP) c = CCAP;
  }
  if (c < 1) c = 1;

  int W = 256; while (W < c) W <<= 1;
  for (int i = c + tid; i < W; i += NTC) cbuf[i] = 0ULL;
  __syncthreads();
  for (int kk = 2; kk <= W; kk <<= 1)
    for (int j = kk >> 1; j > 0; j >>= 1){
      __syncthreads();
      for (int t = tid; t < W; t += NTC){
        int l = t ^ j;
        if (l > t){
          u64 a = cbuf[t], b2 = cbuf[l];
          bool asc = ((t & kk) == 0);
          if (asc ? (a > b2) : (a < b2)){ cbuf[t] = b2; cbuf[l] = a; }
        }
      }
    }
  __syncthreads();

  int mrounds = (MN < c) ? MN : c;
  if (tid < MN){
    if (tid < mrounds){
      u64 w = cbuf[W - 1 - tid];
      out[(size_t)B + (size_t)row*MN + tid] = (fdec((u32)(w >> 32)) - mf) - logZ;
      out[(size_t)B + (size_t)B*MN + (size_t)row*MN + tid] = (float)(~(u32)w);
    } else {
      out[(size_t)B + (size_t)row*MN + tid] = 0.f;
      out[(size_t)B + (size_t)B*MN + (size_t)row*MN + tid] = 0.f;
    }
  }
  __syncthreads();

  const float rep = repetition[row], fr = frequency[row], pr = presence[row];
  const float tp = temperature[row], td = (tp < 1e-5f) ? 1.f : tp;
  for (int i = tid; i < W; i += NTC){
    u64 k = cbuf[i];
    if (k != 0ULL){
      u32 idx = ~(u32)k;
      float x = fdec((u32)(k >> 32));
      u32 info = probe(idx);
      int cv = (int)(info & 0xFFFFu);
      if (info & (1u<<17)) x = NEG_INF_F;
      if ((info & (1u<<16)) || cv > 0) x = (x > 0.f) ? (x / rep) : (x * rep);
      x = x - fr * (float)cv;
      if (cv > 0) x = x - pr;
      x = x / td;
      cbuf[i] = ((u64)fkey(x) << 32) | (u32)~idx;
    }
  }
  for (int kk = 2; kk <= W; kk <<= 1)
    for (int j = kk >> 1; j > 0; j >>= 1){
      __syncthreads();
      for (int t = tid; t < W; t += NTC){
        int l = t ^ j;
        if (l > t){
          u64 a = cbuf[t], b2 = cbuf[l];
          bool asc = ((t & kk) == 0);
          if (asc ? (a > b2) : (a < b2)){ cbuf[t] = b2; cbuf[l] = a; }
        }
      }
    }
  __syncthreads();

  const int trounds = (TOPN < c) ? TOPN : c;
  const u64 half = ((u64)B * (u64)V) >> 1;
  if (tid < trounds){
    u64 w = cbuf[W - 1 - tid];
    float x = fdec((u32)(w >> 32));
    u32 ix = ~(u32)w;
    e_val[tid] = x; e_idx[tid] = ix;
    e_gum[tid] = gumbel_at((u64)row * (u64)V + ix, half);
  }
  __syncthreads();
  if (tid < trounds) e_exp[tid] = expf(e_val[tid] - e_val[0]);
  __syncthreads();
  if (tid == 0){
    int k = top_k[row];
    if (k < 1) k = 1;
    if (k > trounds) k = trounds;
    float kth = e_val[k - 1];
    float Ssum = 0.f; int k2 = 0;
    for (int j = 0; j < trounds; j++){
      if (e_val[j] >= kth){ Ssum += e_exp[j]; k2 = j + 1; } else break;
    }
    const float thr = top_p[row] * Ssum;
    float pref = 0.f, best = __int_as_float(0xff800000);
    u32 besti = e_idx[0];
    for (int j = 0; j < k2; j++){
      bool keep = (j == 0) || (pref < thr);
      pref += e_exp[j];
      if (keep){
        float sc = e_val[j] + e_gum[j];
        if (sc > best){ best = sc; besti = e_idx[j]; }
      }
    }
    out[row] = (float)((tp < 1e-5f) ? e_idx[0] : besti);
  }
}

extern "C" void kernel_launch(void* const* d_in, const int* in_sizes, int n_in,
                              void* d_out, int out_size)
{
  const float* logits = (const float*)d_in[0];
  int B = in_sizes[1];
  int V = in_sizes[0] / B;
  int P = in_sizes[6] / B;
  int O = in_sizes[7] / B;
  int S = in_sizes[9] / B;
  int MN = (out_size / B - 1) / 2;
  if (MN < 0) MN = 0;
  int Vs = (((V + SPLITB - 1) / SPLITB) + 31) & ~31;

  ka_sample<<<B, NTA>>>(logits, V);
  kb_gather<<<B * SPLITB, NTB>>>(logits, V, Vs);

  size_t sh = (size_t)CCAP * sizeof(u64) + (size_t)HCAP * 2 * sizeof(u32);
  cudaFuncSetAttribute(kc_final, cudaFuncAttributeMaxDynamicSharedMemorySize, (int)sh);
  kc_final<<<B, NTC, sh>>>(logits,
      (const float*)d_in[1], (const float*)d_in[2], (const float*)d_in[3],
      (const float*)d_in[4], (const float*)d_in[5],
      (const int*)d_in[6], (const int*)d_in[7], (const int*)d_in[8],
      (const int*)d_in[9], (const int*)d_in[10], (const int*)d_in[11],
      (float*)d_out, B, V, P, O, S, MN);
}